// round 13
// baseline (speedup 1.0000x reference)
#include <cuda_runtime.h>
#include <cuda_fp16.h>
#include <cstddef>
#include <cstdint>

#define NNODES 100000
#define NEDGES 3200000
#define C1 256
#define C2 128
#define SCAN_B 1024
#define NBLK ((NNODES + SCAN_B - 1) / SCAN_B)   // 98

// ---- scratch (static device globals) ----
__device__ int g_cnt   [NNODES];
__device__ int g_rowptr[NNODES];
__device__ int g_cursor[NNODES];
__device__ int g_bsum  [NBLK];
__device__ int g_srclist[NEDGES];
__device__ float g_sdinv[NEDGES];                // dinv[src] parallel to srclist
__device__ __align__(16) float  g_dinv[NNODES];
__device__ __align__(16) __half g_t1h[(size_t)NNODES * C1];  // UNscaled fp16 x@W1
__device__ __align__(16) __half g_hh [(size_t)NNODES * C1];  // fp16 hidden
__device__ __align__(16) __half g_t2h[(size_t)NNODES * C2];  // dinv-scaled fp16 h@[Wmu|Wlv]

// ---------------- CSR build ----------------
__global__ void zero_cnt(int M) {
    int i = blockIdx.x * blockDim.x + threadIdx.x;
    if (i < M) g_cnt[i] = 0;
}
__global__ void count_deg(const int* __restrict__ ei, int E) {
    int e = blockIdx.x * blockDim.x + threadIdx.x;
    if (e < E) atomicAdd(&g_cnt[ei[(size_t)E + e]], 1);
}
__global__ __launch_bounds__(SCAN_B) void scan_local(int M) {
    __shared__ int sh[SCAN_B];
    int tid = threadIdx.x;
    int i = blockIdx.x * SCAN_B + tid;
    int v = (i < M) ? g_cnt[i] : 0;
    if (i < M) g_dinv[i] = rsqrtf((float)(v + 1));
    sh[tid] = v;
    __syncthreads();
#pragma unroll
    for (int off = 1; off < SCAN_B; off <<= 1) {
        int t = (tid >= off) ? sh[tid - off] : 0;
        __syncthreads();
        sh[tid] += t;
        __syncthreads();
    }
    if (i < M) g_rowptr[i] = sh[tid] - v;
    if (tid == SCAN_B - 1) g_bsum[blockIdx.x] = sh[tid];
}
__global__ void scan_apply(int M) {
    __shared__ int s_off;
    int seg = (blockIdx.x * 256) / SCAN_B;
    if (threadIdx.x < 32) {
        int acc = 0;
        for (int j = threadIdx.x; j < seg; j += 32) acc += g_bsum[j];
#pragma unroll
        for (int o = 16; o; o >>= 1) acc += __shfl_down_sync(0xffffffff, acc, o);
        if (threadIdx.x == 0) s_off = acc;
    }
    __syncthreads();
    int i = blockIdx.x * 256 + threadIdx.x;
    if (i < M) {
        int r = g_rowptr[i] + s_off;
        g_rowptr[i] = r;
        g_cursor[i] = r;
    }
}
__global__ void fill_csr(const int* __restrict__ ei, int E) {
    int e = blockIdx.x * blockDim.x + threadIdx.x;
    if (e < E) {
        int s = ei[e];
        int d = ei[(size_t)E + e];
        int pos = atomicAdd(&g_cursor[d], 1);
        g_srclist[pos] = s;
        g_sdinv[pos] = g_dinv[s];
    }
}

// ---------------- fp16 MMA GEMM with ldmatrix (A fp32 or fp16) ----------------
#define TBM 128
#define TBN 64
#define TBK 32
#define AST 40
#define BST 72

__device__ __forceinline__ void ldsm_x4(uint32_t& r0, uint32_t& r1, uint32_t& r2, uint32_t& r3,
                                        const void* p) {
    uint32_t addr = (uint32_t)__cvta_generic_to_shared(p);
    asm volatile("ldmatrix.sync.aligned.m8n8.x4.shared.b16 {%0,%1,%2,%3}, [%4];"
                 : "=r"(r0), "=r"(r1), "=r"(r2), "=r"(r3) : "r"(addr));
}
__device__ __forceinline__ void ldsm_x2t(uint32_t& r0, uint32_t& r1, const void* p) {
    uint32_t addr = (uint32_t)__cvta_generic_to_shared(p);
    asm volatile("ldmatrix.sync.aligned.m8n8.x2.trans.shared.b16 {%0,%1}, [%2];"
                 : "=r"(r0), "=r"(r1) : "r"(addr));
}

template <bool AHALF>
__global__ __launch_bounds__(256) void gemm_h16(
    const void* __restrict__ Ap, int lda,
    const float* __restrict__ B1, const float* __restrict__ B2,
    int ldb, int nby, int nby1,
    __half* __restrict__ Ct, int ldc,
    const float* __restrict__ dinv, int M, int K)
{
    __shared__ __align__(16) __half As[2][TBM][AST];
    __shared__ __align__(16) __half Bs[2][TBK][BST];

    const int tid = threadIdx.x;
    const int lane = tid & 31;
    const int warp = tid >> 5;
    const int wm = warp & 3;
    const int wn = warp >> 2;
    const int gid = lane >> 2;
    const int q = lane & 3;

    const int by = blockIdx.x % nby;
    const int bx = blockIdx.x / nby;
    const int row0 = bx * TBM;

    const float* B = (by < nby1) ? B1 : B2;
    const int bcol0 = (by < nby1) ? by * TBN : (by - nby1) * TBN;
    const int ocol0 = by * TBN;

    float c[2][4][4];
#pragma unroll
    for (int mt = 0; mt < 2; mt++)
#pragma unroll
        for (int nt = 0; nt < 4; nt++)
#pragma unroll
            for (int r = 0; r < 4; r++) c[mt][nt][r] = 0.f;

    const int nk = K / TBK;
    float4 Av[4];
    uint4  Ah[2];
    float4 Bv[2];

    auto load_tile = [&](int t) {
        int k0 = t * TBK;
        if (AHALF) {
            const __half* A = (const __half*)Ap;
#pragma unroll
            for (int i = 0; i < 2; i++) {
                int idx = tid + i * 256;
                int r = idx >> 2;
                int c8 = (idx & 3) << 3;
                int gr = row0 + r;
                Ah[i] = (gr < M) ? *(const uint4*)(A + (size_t)gr * lda + k0 + c8)
                                 : make_uint4(0, 0, 0, 0);
            }
        } else {
            const float* A = (const float*)Ap;
#pragma unroll
            for (int i = 0; i < 4; i++) {
                int idx = tid + i * 256;
                int r = idx >> 3;
                int c4 = (idx & 7) << 2;
                int gr = row0 + r;
                Av[i] = (gr < M) ? *(const float4*)(A + (size_t)gr * lda + k0 + c4)
                                 : make_float4(0.f, 0.f, 0.f, 0.f);
            }
        }
#pragma unroll
        for (int i = 0; i < 2; i++) {
            int idx = tid + i * 256;
            int r = idx >> 4;
            int c4 = (idx & 15) << 2;
            Bv[i] = *(const float4*)(B + (size_t)(k0 + r) * ldb + bcol0 + c4);
        }
    };
    auto store_tile = [&](int buf) {
        if (AHALF) {
#pragma unroll
            for (int i = 0; i < 2; i++) {
                int idx = tid + i * 256;
                int r = idx >> 2;
                int c8 = (idx & 3) << 3;
                *(uint4*)&As[buf][r][c8] = Ah[i];
            }
        } else {
#pragma unroll
            for (int i = 0; i < 4; i++) {
                int idx = tid + i * 256;
                int r = idx >> 3;
                int c4 = (idx & 7) << 2;
                __half2 h01 = __floats2half2_rn(Av[i].x, Av[i].y);
                __half2 h23 = __floats2half2_rn(Av[i].z, Av[i].w);
                uint2 u = make_uint2(*(uint32_t*)&h01, *(uint32_t*)&h23);
                *(uint2*)&As[buf][r][c4] = u;
            }
        }
#pragma unroll
        for (int i = 0; i < 2; i++) {
            int idx = tid + i * 256;
            int r = idx >> 4;
            int c4 = (idx & 15) << 2;
            __half2 h01 = __floats2half2_rn(Bv[i].x, Bv[i].y);
            __half2 h23 = __floats2half2_rn(Bv[i].z, Bv[i].w);
            uint2 u = make_uint2(*(uint32_t*)&h01, *(uint32_t*)&h23);
            *(uint2*)&Bs[buf][r][c4] = u;
        }
    };

    load_tile(0);
    store_tile(0);
    __syncthreads();

    const int a_row = (lane & 15);
    const int a_koff = (lane >> 4) << 3;
    const int b_krow = (lane & 15);

    for (int t = 0; t < nk; t++) {
        int buf = t & 1;
        if (t + 1 < nk) load_tile(t + 1);

#pragma unroll
        for (int ks = 0; ks < TBK / 16; ks++) {
            int kb = ks * 16;
            uint32_t a[2][4], b[4][2];
#pragma unroll
            for (int mt = 0; mt < 2; mt++) {
                const __half* p = &As[buf][wm * 32 + mt * 16 + a_row][kb + a_koff];
                ldsm_x4(a[mt][0], a[mt][1], a[mt][2], a[mt][3], p);
            }
#pragma unroll
            for (int nt = 0; nt < 4; nt++) {
                const __half* p = &Bs[buf][kb + b_krow][wn * 32 + nt * 8];
                ldsm_x2t(b[nt][0], b[nt][1], p);
            }
#pragma unroll
            for (int mt = 0; mt < 2; mt++)
#pragma unroll
                for (int nt = 0; nt < 4; nt++)
                    asm volatile(
                        "mma.sync.aligned.m16n8k16.row.col.f32.f16.f16.f32 "
                        "{%0,%1,%2,%3}, {%4,%5,%6,%7}, {%8,%9}, {%0,%1,%2,%3};"
                        : "+f"(c[mt][nt][0]), "+f"(c[mt][nt][1]),
                          "+f"(c[mt][nt][2]), "+f"(c[mt][nt][3])
                        : "r"(a[mt][0]), "r"(a[mt][1]), "r"(a[mt][2]), "r"(a[mt][3]),
                          "r"(b[nt][0]), "r"(b[nt][1]));
        }

        if (t + 1 < nk) {
            store_tile(buf ^ 1);
            __syncthreads();
        }
    }

#pragma unroll
    for (int mt = 0; mt < 2; mt++) {
        int r0 = row0 + wm * 32 + mt * 16 + gid;
        int r1 = r0 + 8;
        float dv0 = 1.f, dv1 = 1.f;
        if (dinv) {
            dv0 = (r0 < M) ? dinv[r0] : 0.f;
            dv1 = (r1 < M) ? dinv[r1] : 0.f;
        }
#pragma unroll
        for (int nt = 0; nt < 4; nt++) {
            int cc = ocol0 + wn * 32 + nt * 8 + 2 * q;
            if (r0 < M)
                *(__half2*)(Ct + (size_t)r0 * ldc + cc) =
                    __floats2half2_rn(c[mt][nt][0] * dv0, c[mt][nt][1] * dv0);
            if (r1 < M)
                *(__half2*)(Ct + (size_t)r1 * ldc + cc) =
                    __floats2half2_rn(c[mt][nt][2] * dv1, c[mt][nt][3] * dv1);
        }
    }
}

// ---- fp16 accumulate helpers ----
__device__ __forceinline__ void hacc8s(float* a, uint4 u, float dv) {
    const __half2* hp = (const __half2*)&u;
#pragma unroll
    for (int i = 0; i < 4; i++) {
        float2 f = __half22float2(hp[i]);
        a[2 * i]     = fmaf(dv, f.x, a[2 * i]);
        a[2 * i + 1] = fmaf(dv, f.y, a[2 * i + 1]);
    }
}
__device__ __forceinline__ void hacc4(float* a, uint2 u) {
    const __half2* hp = (const __half2*)&u;
#pragma unroll
    for (int i = 0; i < 2; i++) {
        float2 f = __half22float2(hp[i]);
        a[2 * i] += f.x;
        a[2 * i + 1] += f.y;
    }
}

// ---------------- gather layer 1 (uniform loads, 8-deep MLP, PDL, side dinv) ----------------
__global__ __launch_bounds__(256) void gather1(const float* __restrict__ b1, int M)
{
    // PDL prologue: CSR metadata only (guarded by the retained event edge, not gemm1)
    int w = (blockIdx.x * blockDim.x + threadIdx.x) >> 5;
    int lane = threadIdx.x & 31;
    int base = 0, deg = 0;
    float dvw = 0.f;
    if (w < M) {
        base = g_rowptr[w];
        deg = g_cnt[w];
        dvw = g_dinv[w];
    }
    cudaGridDependencySynchronize();   // t1h (gemm1 output) visible after this
    if (w >= M) return;

    float a[8];
#pragma unroll
    for (int i = 0; i < 8; i++) a[i] = 0.f;
    hacc8s(a, ((const uint4*)(g_t1h + (size_t)w * C1))[lane], dvw);

    const int* __restrict__ sl = g_srclist + base;
    const float* __restrict__ sd = g_sdinv + base;
    int k = 0;
    for (; k + 8 <= deg; k += 8) {
        int s[8];
        float d[8];
        uint4 u[8];
#pragma unroll
        for (int i = 0; i < 8; i++) s[i] = __ldg(sl + k + i);
#pragma unroll
        for (int i = 0; i < 8; i++) d[i] = __ldg(sd + k + i);   // independent stream
#pragma unroll
        for (int i = 0; i < 8; i++) u[i] = ((const uint4*)(g_t1h + (size_t)s[i] * C1))[lane];
#pragma unroll
        for (int i = 0; i < 8; i++) hacc8s(a, u[i], d[i]);
    }
    for (; k + 4 <= deg; k += 4) {
        int s0 = __ldg(sl + k);
        int s1 = __ldg(sl + k + 1);
        int s2 = __ldg(sl + k + 2);
        int s3 = __ldg(sl + k + 3);
        float d0 = __ldg(sd + k);
        float d1 = __ldg(sd + k + 1);
        float d2 = __ldg(sd + k + 2);
        float d3 = __ldg(sd + k + 3);
        uint4 u0 = ((const uint4*)(g_t1h + (size_t)s0 * C1))[lane];
        uint4 u1 = ((const uint4*)(g_t1h + (size_t)s1 * C1))[lane];
        uint4 u2 = ((const uint4*)(g_t1h + (size_t)s2 * C1))[lane];
        uint4 u3 = ((const uint4*)(g_t1h + (size_t)s3 * C1))[lane];
        hacc8s(a, u0, d0); hacc8s(a, u1, d1); hacc8s(a, u2, d2); hacc8s(a, u3, d3);
    }
    for (; k < deg; k++) {
        int s0 = __ldg(sl + k);
        float d0 = __ldg(sd + k);
        hacc8s(a, ((const uint4*)(g_t1h + (size_t)s0 * C1))[lane], d0);
    }

    float4 bb0 = ((const float4*)b1)[lane * 2];
    float4 bb1 = ((const float4*)b1)[lane * 2 + 1];
    float o[8];
    o[0] = fmaxf(fmaf(dvw, a[0], bb0.x), 0.f);
    o[1] = fmaxf(fmaf(dvw, a[1], bb0.y), 0.f);
    o[2] = fmaxf(fmaf(dvw, a[2], bb0.z), 0.f);
    o[3] = fmaxf(fmaf(dvw, a[3], bb0.w), 0.f);
    o[4] = fmaxf(fmaf(dvw, a[4], bb1.x), 0.f);
    o[5] = fmaxf(fmaf(dvw, a[5], bb1.y), 0.f);
    o[6] = fmaxf(fmaf(dvw, a[6], bb1.z), 0.f);
    o[7] = fmaxf(fmaf(dvw, a[7], bb1.w), 0.f);
    __half2 h0 = __floats2half2_rn(o[0], o[1]);
    __half2 h1 = __floats2half2_rn(o[2], o[3]);
    __half2 h2 = __floats2half2_rn(o[4], o[5]);
    __half2 h3 = __floats2half2_rn(o[6], o[7]);
    uint4 u = make_uint4(*(uint32_t*)&h0, *(uint32_t*)&h1, *(uint32_t*)&h2, *(uint32_t*)&h3);
    ((uint4*)(g_hh + (size_t)w * C1))[lane] = u;
}

// ---------------- fused gather2 + head (uniform loads, PDL) ----------------
__global__ __launch_bounds__(1024) void gather2_head(
    const float* __restrict__ b_mu, const float* __restrict__ b_lv,
    const float* __restrict__ W_c, const float* __restrict__ b_c,
    const float* __restrict__ eps,
    float* __restrict__ out, int M)
{
    __shared__ float sWc[64 * 64];
    __shared__ float sz[32][64];
    int tid = threadIdx.x;
    for (int i = tid; i < 64 * 64; i += 1024) sWc[i] = W_c[i];
    cudaGridDependencySynchronize();
    __syncthreads();

    int w = (blockIdx.x * blockDim.x + tid) >> 5;
    if (w >= M) return;
    int lane = tid & 31;
    int wid = (tid >> 5);
    int base = g_rowptr[w];
    int deg = g_cnt[w];

    float a[4] = {0.f, 0.f, 0.f, 0.f};
    hacc4(a, ((const uint2*)(g_t2h + (size_t)w * C2))[lane]);

    const int* __restrict__ sl = g_srclist + base;
    int k = 0;
    for (; k + 4 <= deg; k += 4) {
        int s0 = __ldg(sl + k);
        int s1 = __ldg(sl + k + 1);
        int s2 = __ldg(sl + k + 2);
        int s3 = __ldg(sl + k + 3);
        uint2 u0 = ((const uint2*)(g_t2h + (size_t)s0 * C2))[lane];
        uint2 u1 = ((const uint2*)(g_t2h + (size_t)s1 * C2))[lane];
        uint2 u2 = ((const uint2*)(g_t2h + (size_t)s2 * C2))[lane];
        uint2 u3 = ((const uint2*)(g_t2h + (size_t)s3 * C2))[lane];
        hacc4(a, u0); hacc4(a, u1); hacc4(a, u2); hacc4(a, u3);
    }
    for (; k < deg; k++) {
        int s0 = __ldg(sl + k);
        hacc4(a, ((const uint2*)(g_t2h + (size_t)s0 * C2))[lane]);
    }

    float dv = g_dinv[w];
    bool is_mu = lane < 16;
    int cm = is_mu ? lane * 4 : (lane - 16) * 4;
    float4 bb = is_mu ? ((const float4*)b_mu)[cm >> 2] : ((const float4*)b_lv)[cm >> 2];
    float v[4];
    v[0] = fmaf(dv, a[0], bb.x);
    v[1] = fmaf(dv, a[1], bb.y);
    v[2] = fmaf(dv, a[2], bb.z);
    v[3] = fmaf(dv, a[3], bb.w);

    size_t MO = (size_t)M * 64;
    float* dst = is_mu ? (out + MO + (size_t)w * 64 + cm)
                       : (out + 2 * MO + (size_t)w * 64 + cm);
    *(float4*)dst = make_float4(v[0], v[1], v[2], v[3]);

    float lv0 = __shfl_sync(0xffffffff, v[0], lane + 16);
    float lv1 = __shfl_sync(0xffffffff, v[1], lane + 16);
    float lv2 = __shfl_sync(0xffffffff, v[2], lane + 16);
    float lv3 = __shfl_sync(0xffffffff, v[3], lane + 16);
    if (is_mu) {
        float4 ep = *(const float4*)(eps + (size_t)w * 64 + cm);
        sz[wid][cm + 0] = fmaf(ep.x, __expf(0.5f * lv0), v[0]);
        sz[wid][cm + 1] = fmaf(ep.y, __expf(0.5f * lv1), v[1]);
        sz[wid][cm + 2] = fmaf(ep.z, __expf(0.5f * lv2), v[2]);
        sz[wid][cm + 3] = fmaf(ep.w, __expf(0.5f * lv3), v[3]);
    }
    __syncwarp();

    float s1 = b_c[lane];
    float s2 = b_c[lane + 32];
#pragma unroll 16
    for (int c = 0; c < 64; c++) {
        float zc = sz[wid][c];
        s1 = fmaf(zc, sWc[c * 64 + lane], s1);
        s2 = fmaf(zc, sWc[c * 64 + lane + 32], s2);
    }
    out[(size_t)w * 64 + lane] = s1;
    out[(size_t)w * 64 + lane + 32] = s2;
}

extern "C" void kernel_launch(void* const* d_in, const int* in_sizes, int n_in,
                              void* d_out, int out_size) {
    const float* x    = (const float*)d_in[0];
    const int*   ei   = (const int*)d_in[1];
    const float* W1   = (const float*)d_in[2];
    const float* b1   = (const float*)d_in[3];
    const float* W_mu = (const float*)d_in[4];
    const float* b_mu = (const float*)d_in[5];
    const float* W_lv = (const float*)d_in[6];
    const float* b_lv = (const float*)d_in[7];
    const float* W_c  = (const float*)d_in[8];
    const float* b_c  = (const float*)d_in[9];
    const float* eps  = (const float*)d_in[10];
    float* out = (float*)d_out;

    const int M = in_sizes[0] / 512;   // 100000
    const int E = in_sizes[1] / 2;     // 3200000

    float* dinv;
    __half *t1h, *hh, *t2h;
    cudaGetSymbolAddress((void**)&dinv, g_dinv);
    cudaGetSymbolAddress((void**)&t1h,  g_t1h);
    cudaGetSymbolAddress((void**)&hh,   g_hh);
    cudaGetSymbolAddress((void**)&t2h,  g_t2h);

    static cudaStream_t s2 = nullptr;
    static cudaEvent_t ev_fork = nullptr, ev_csr = nullptr;
    if (!s2) {
        cudaStreamCreateWithFlags(&s2, cudaStreamNonBlocking);
        cudaEventCreateWithFlags(&ev_fork, cudaEventDisableTiming);
        cudaEventCreateWithFlags(&ev_csr,  cudaEventDisableTiming);
    }

    // ---- fork: CSR build on s2, GEMM1 on main ----
    cudaEventRecord(ev_fork, 0);
    cudaStreamWaitEvent(s2, ev_fork, 0);

    zero_cnt  <<<(M + 255) / 256, 256, 0, s2>>>(M);
    count_deg <<<(E + 511) / 512, 512, 0, s2>>>(ei, E);
    scan_local<<<NBLK, SCAN_B, 0, s2>>>(M);
    scan_apply<<<(M + 255) / 256, 256, 0, s2>>>(M);
    fill_csr  <<<(E + 511) / 512, 512, 0, s2>>>(ei, E);
    cudaEventRecord(ev_csr, s2);

    // GEMM1: t1h = fp16(x @ W1), swizzled 1-D grid
    {
        int nbx = (M + TBM - 1) / TBM;
        int nby = C1 / TBN;   // 4
        gemm_h16<false><<<nbx * nby, 256>>>(x, 512, W1, W1, C1, nby, nby,
                                            t1h, C1, nullptr, M, 512);
    }

    cudaStreamWaitEvent(0, ev_csr, 0);

    // gather1 with PDL: CSR-metadata prologue overlaps gemm1 tail
    {
        cudaLaunchConfig_t cfg = {};
        cfg.gridDim = dim3((M * 32 + 255) / 256);
        cfg.blockDim = dim3(256);
        cfg.dynamicSmemBytes = 0;
        cfg.stream = 0;
        cudaLaunchAttribute at[1];
        at[0].id = cudaLaunchAttributeProgrammaticStreamSerialization;
        at[0].val.programmaticStreamSerializationAllowed = 1;
        cfg.attrs = at;
        cfg.numAttrs = 1;
        cudaLaunchKernelEx(&cfg, gather1, b1, M);
    }

    // GEMM2: t2h = dinv * (hh @ [W_mu | W_lv])
    {
        int nbx = (M + TBM - 1) / TBM;
        gemm_h16<true><<<nbx * 2, 256>>>(hh, C1, W_mu, W_lv, 64, 2, 1,
                                         t2h, C2, dinv, M, C1);
    }

    // gather2_head with PDL: prologue (Wc staging) overlaps gemm2 tail
    {
        cudaLaunchConfig_t cfg = {};
        cfg.gridDim = dim3((M * 32 + 1023) / 1024);
        cfg.blockDim = dim3(1024);
        cfg.dynamicSmemBytes = 0;
        cfg.stream = 0;
        cudaLaunchAttribute at[1];
        at[0].id = cudaLaunchAttributeProgrammaticStreamSerialization;
        at[0].val.programmaticStreamSerializationAllowed = 1;
        cfg.attrs = at;
        cfg.numAttrs = 1;
        cudaLaunchKernelEx(&cfg, gather2_head, b_mu, b_lv, W_c, b_c, eps, out, M);
    }
}

// round 14
// speedup vs baseline: 1.1048x; 1.1048x over previous
#include <cuda_runtime.h>
#include <cuda_fp16.h>
#include <cstddef>
#include <cstdint>

#define NNODES 100000
#define NEDGES 3200000
#define C1 256
#define C2 128
#define SCAN_B 1024
#define NBLK ((NNODES + SCAN_B - 1) / SCAN_B)   // 98

// ---- scratch (static device globals) ----
__device__ int g_cnt   [NNODES];
__device__ int g_rowptr[NNODES];
__device__ int g_cursor[NNODES];
__device__ int g_bsum  [NBLK];
__device__ int g_srclist[NEDGES];
__device__ __align__(16) float  g_dinv[NNODES];
__device__ __align__(16) __half g_t1h[(size_t)NNODES * C1];  // UNscaled fp16 x@W1
__device__ __align__(16) __half g_hh [(size_t)NNODES * C1];  // fp16 hidden
__device__ __align__(16) __half g_t2h[(size_t)NNODES * C2];  // dinv-scaled fp16 h@[Wmu|Wlv]

// ---------------- CSR build ----------------
__global__ void zero_cnt(int M) {
    int i = blockIdx.x * blockDim.x + threadIdx.x;
    if (i < M) g_cnt[i] = 0;
}
__global__ void count_deg(const int* __restrict__ ei, int E) {
    int e = blockIdx.x * blockDim.x + threadIdx.x;
    if (e < E) atomicAdd(&g_cnt[ei[(size_t)E + e]], 1);
}
__global__ __launch_bounds__(SCAN_B) void scan_local(int M) {
    __shared__ int sh[SCAN_B];
    int tid = threadIdx.x;
    int i = blockIdx.x * SCAN_B + tid;
    int v = (i < M) ? g_cnt[i] : 0;
    if (i < M) g_dinv[i] = rsqrtf((float)(v + 1));
    sh[tid] = v;
    __syncthreads();
#pragma unroll
    for (int off = 1; off < SCAN_B; off <<= 1) {
        int t = (tid >= off) ? sh[tid - off] : 0;
        __syncthreads();
        sh[tid] += t;
        __syncthreads();
    }
    if (i < M) g_rowptr[i] = sh[tid] - v;
    if (tid == SCAN_B - 1) g_bsum[blockIdx.x] = sh[tid];
}
__global__ void scan_apply(int M) {
    __shared__ int s_off;
    int seg = (blockIdx.x * 256) / SCAN_B;
    if (threadIdx.x < 32) {
        int acc = 0;
        for (int j = threadIdx.x; j < seg; j += 32) acc += g_bsum[j];
#pragma unroll
        for (int o = 16; o; o >>= 1) acc += __shfl_down_sync(0xffffffff, acc, o);
        if (threadIdx.x == 0) s_off = acc;
    }
    __syncthreads();
    int i = blockIdx.x * 256 + threadIdx.x;
    if (i < M) {
        int r = g_rowptr[i] + s_off;
        g_rowptr[i] = r;
        g_cursor[i] = r;
    }
}
__global__ void fill_csr(const int* __restrict__ ei, int E) {
    int e = blockIdx.x * blockDim.x + threadIdx.x;
    if (e < E) {
        int s = ei[e];
        int d = ei[(size_t)E + e];
        int pos = atomicAdd(&g_cursor[d], 1);
        g_srclist[pos] = s;
    }
}

// ---------------- fp16 MMA GEMM with ldmatrix (A fp32 or fp16) ----------------
#define TBM 128
#define TBN 64
#define TBK 32
#define AST 40
#define BST 72

__device__ __forceinline__ void ldsm_x4(uint32_t& r0, uint32_t& r1, uint32_t& r2, uint32_t& r3,
                                        const void* p) {
    uint32_t addr = (uint32_t)__cvta_generic_to_shared(p);
    asm volatile("ldmatrix.sync.aligned.m8n8.x4.shared.b16 {%0,%1,%2,%3}, [%4];"
                 : "=r"(r0), "=r"(r1), "=r"(r2), "=r"(r3) : "r"(addr));
}
__device__ __forceinline__ void ldsm_x2t(uint32_t& r0, uint32_t& r1, const void* p) {
    uint32_t addr = (uint32_t)__cvta_generic_to_shared(p);
    asm volatile("ldmatrix.sync.aligned.m8n8.x2.trans.shared.b16 {%0,%1}, [%2];"
                 : "=r"(r0), "=r"(r1) : "r"(addr));
}

template <bool AHALF>
__global__ __launch_bounds__(256) void gemm_h16(
    const void* __restrict__ Ap, int lda,
    const float* __restrict__ B1, const float* __restrict__ B2,
    int ldb, int nby, int nby1,
    __half* __restrict__ Ct, int ldc,
    const float* __restrict__ dinv, int M, int K)
{
    __shared__ __align__(16) __half As[2][TBM][AST];
    __shared__ __align__(16) __half Bs[2][TBK][BST];

    const int tid = threadIdx.x;
    const int lane = tid & 31;
    const int warp = tid >> 5;
    const int wm = warp & 3;
    const int wn = warp >> 2;
    const int gid = lane >> 2;
    const int q = lane & 3;

    const int by = blockIdx.x % nby;
    const int bx = blockIdx.x / nby;
    const int row0 = bx * TBM;

    const float* B = (by < nby1) ? B1 : B2;
    const int bcol0 = (by < nby1) ? by * TBN : (by - nby1) * TBN;
    const int ocol0 = by * TBN;

    float c[2][4][4];
#pragma unroll
    for (int mt = 0; mt < 2; mt++)
#pragma unroll
        for (int nt = 0; nt < 4; nt++)
#pragma unroll
            for (int r = 0; r < 4; r++) c[mt][nt][r] = 0.f;

    const int nk = K / TBK;
    float4 Av[4];
    uint4  Ah[2];
    float4 Bv[2];

    auto load_tile = [&](int t) {
        int k0 = t * TBK;
        if (AHALF) {
            const __half* A = (const __half*)Ap;
#pragma unroll
            for (int i = 0; i < 2; i++) {
                int idx = tid + i * 256;
                int r = idx >> 2;
                int c8 = (idx & 3) << 3;
                int gr = row0 + r;
                Ah[i] = (gr < M) ? *(const uint4*)(A + (size_t)gr * lda + k0 + c8)
                                 : make_uint4(0, 0, 0, 0);
            }
        } else {
            const float* A = (const float*)Ap;
#pragma unroll
            for (int i = 0; i < 4; i++) {
                int idx = tid + i * 256;
                int r = idx >> 3;
                int c4 = (idx & 7) << 2;
                int gr = row0 + r;
                Av[i] = (gr < M) ? *(const float4*)(A + (size_t)gr * lda + k0 + c4)
                                 : make_float4(0.f, 0.f, 0.f, 0.f);
            }
        }
#pragma unroll
        for (int i = 0; i < 2; i++) {
            int idx = tid + i * 256;
            int r = idx >> 4;
            int c4 = (idx & 15) << 2;
            Bv[i] = *(const float4*)(B + (size_t)(k0 + r) * ldb + bcol0 + c4);
        }
    };
    auto store_tile = [&](int buf) {
        if (AHALF) {
#pragma unroll
            for (int i = 0; i < 2; i++) {
                int idx = tid + i * 256;
                int r = idx >> 2;
                int c8 = (idx & 3) << 3;
                *(uint4*)&As[buf][r][c8] = Ah[i];
            }
        } else {
#pragma unroll
            for (int i = 0; i < 4; i++) {
                int idx = tid + i * 256;
                int r = idx >> 3;
                int c4 = (idx & 7) << 2;
                __half2 h01 = __floats2half2_rn(Av[i].x, Av[i].y);
                __half2 h23 = __floats2half2_rn(Av[i].z, Av[i].w);
                uint2 u = make_uint2(*(uint32_t*)&h01, *(uint32_t*)&h23);
                *(uint2*)&As[buf][r][c4] = u;
            }
        }
#pragma unroll
        for (int i = 0; i < 2; i++) {
            int idx = tid + i * 256;
            int r = idx >> 4;
            int c4 = (idx & 15) << 2;
            __half2 h01 = __floats2half2_rn(Bv[i].x, Bv[i].y);
            __half2 h23 = __floats2half2_rn(Bv[i].z, Bv[i].w);
            uint2 u = make_uint2(*(uint32_t*)&h01, *(uint32_t*)&h23);
            *(uint2*)&Bs[buf][r][c4] = u;
        }
    };

    load_tile(0);
    store_tile(0);
    __syncthreads();

    const int a_row = (lane & 15);
    const int a_koff = (lane >> 4) << 3;
    const int b_krow = (lane & 15);

    for (int t = 0; t < nk; t++) {
        int buf = t & 1;
        if (t + 1 < nk) load_tile(t + 1);

#pragma unroll
        for (int ks = 0; ks < TBK / 16; ks++) {
            int kb = ks * 16;
            uint32_t a[2][4], b[4][2];
#pragma unroll
            for (int mt = 0; mt < 2; mt++) {
                const __half* p = &As[buf][wm * 32 + mt * 16 + a_row][kb + a_koff];
                ldsm_x4(a[mt][0], a[mt][1], a[mt][2], a[mt][3], p);
            }
#pragma unroll
            for (int nt = 0; nt < 4; nt++) {
                const __half* p = &Bs[buf][kb + b_krow][wn * 32 + nt * 8];
                ldsm_x2t(b[nt][0], b[nt][1], p);
            }
#pragma unroll
            for (int mt = 0; mt < 2; mt++)
#pragma unroll
                for (int nt = 0; nt < 4; nt++)
                    asm volatile(
                        "mma.sync.aligned.m16n8k16.row.col.f32.f16.f16.f32 "
                        "{%0,%1,%2,%3}, {%4,%5,%6,%7}, {%8,%9}, {%0,%1,%2,%3};"
                        : "+f"(c[mt][nt][0]), "+f"(c[mt][nt][1]),
                          "+f"(c[mt][nt][2]), "+f"(c[mt][nt][3])
                        : "r"(a[mt][0]), "r"(a[mt][1]), "r"(a[mt][2]), "r"(a[mt][3]),
                          "r"(b[nt][0]), "r"(b[nt][1]));
        }

        if (t + 1 < nk) {
            store_tile(buf ^ 1);
            __syncthreads();
        }
    }

#pragma unroll
    for (int mt = 0; mt < 2; mt++) {
        int r0 = row0 + wm * 32 + mt * 16 + gid;
        int r1 = r0 + 8;
        float dv0 = 1.f, dv1 = 1.f;
        if (dinv) {
            dv0 = (r0 < M) ? dinv[r0] : 0.f;
            dv1 = (r1 < M) ? dinv[r1] : 0.f;
        }
#pragma unroll
        for (int nt = 0; nt < 4; nt++) {
            int cc = ocol0 + wn * 32 + nt * 8 + 2 * q;
            if (r0 < M)
                *(__half2*)(Ct + (size_t)r0 * ldc + cc) =
                    __floats2half2_rn(c[mt][nt][0] * dv0, c[mt][nt][1] * dv0);
            if (r1 < M)
                *(__half2*)(Ct + (size_t)r1 * ldc + cc) =
                    __floats2half2_rn(c[mt][nt][2] * dv1, c[mt][nt][3] * dv1);
        }
    }
}

// ---- fp16 accumulate helpers ----
__device__ __forceinline__ void hacc8s(float* a, uint4 u, float dv) {
    const __half2* hp = (const __half2*)&u;
#pragma unroll
    for (int i = 0; i < 4; i++) {
        float2 f = __half22float2(hp[i]);
        a[2 * i]     = fmaf(dv, f.x, a[2 * i]);
        a[2 * i + 1] = fmaf(dv, f.y, a[2 * i + 1]);
    }
}
__device__ __forceinline__ void hacc4(float* a, uint2 u) {
    const __half2* hp = (const __half2*)&u;
#pragma unroll
    for (int i = 0; i < 2; i++) {
        float2 f = __half22float2(hp[i]);
        a[2 * i] += f.x;
        a[2 * i + 1] += f.y;
    }
}

// ---------------- gather layer 1 (uniform loads, 8-deep MLP) ----------------
__global__ __launch_bounds__(256) void gather1(const float* __restrict__ b1, int M)
{
    int w = (blockIdx.x * blockDim.x + threadIdx.x) >> 5;
    if (w >= M) return;
    int lane = threadIdx.x & 31;
    int base = g_rowptr[w];
    int deg = g_cnt[w];
    float dvw = g_dinv[w];

    float a[8];
#pragma unroll
    for (int i = 0; i < 8; i++) a[i] = 0.f;
    hacc8s(a, ((const uint4*)(g_t1h + (size_t)w * C1))[lane], dvw);

    const int* __restrict__ sl = g_srclist + base;
    int k = 0;
    for (; k + 8 <= deg; k += 8) {
        int s[8];
        float d[8];
        uint4 u[8];
#pragma unroll
        for (int i = 0; i < 8; i++) s[i] = __ldg(sl + k + i);
#pragma unroll
        for (int i = 0; i < 8; i++) d[i] = __ldg(g_dinv + s[i]);
#pragma unroll
        for (int i = 0; i < 8; i++) u[i] = ((const uint4*)(g_t1h + (size_t)s[i] * C1))[lane];
#pragma unroll
        for (int i = 0; i < 8; i++) hacc8s(a, u[i], d[i]);
    }
    for (; k + 4 <= deg; k += 4) {
        int s0 = __ldg(sl + k);
        int s1 = __ldg(sl + k + 1);
        int s2 = __ldg(sl + k + 2);
        int s3 = __ldg(sl + k + 3);
        float d0 = __ldg(g_dinv + s0);
        float d1 = __ldg(g_dinv + s1);
        float d2 = __ldg(g_dinv + s2);
        float d3 = __ldg(g_dinv + s3);
        uint4 u0 = ((const uint4*)(g_t1h + (size_t)s0 * C1))[lane];
        uint4 u1 = ((const uint4*)(g_t1h + (size_t)s1 * C1))[lane];
        uint4 u2 = ((const uint4*)(g_t1h + (size_t)s2 * C1))[lane];
        uint4 u3 = ((const uint4*)(g_t1h + (size_t)s3 * C1))[lane];
        hacc8s(a, u0, d0); hacc8s(a, u1, d1); hacc8s(a, u2, d2); hacc8s(a, u3, d3);
    }
    for (; k < deg; k++) {
        int s0 = __ldg(sl + k);
        float d0 = __ldg(g_dinv + s0);
        hacc8s(a, ((const uint4*)(g_t1h + (size_t)s0 * C1))[lane], d0);
    }

    float4 bb0 = ((const float4*)b1)[lane * 2];
    float4 bb1 = ((const float4*)b1)[lane * 2 + 1];
    float o[8];
    o[0] = fmaxf(fmaf(dvw, a[0], bb0.x), 0.f);
    o[1] = fmaxf(fmaf(dvw, a[1], bb0.y), 0.f);
    o[2] = fmaxf(fmaf(dvw, a[2], bb0.z), 0.f);
    o[3] = fmaxf(fmaf(dvw, a[3], bb0.w), 0.f);
    o[4] = fmaxf(fmaf(dvw, a[4], bb1.x), 0.f);
    o[5] = fmaxf(fmaf(dvw, a[5], bb1.y), 0.f);
    o[6] = fmaxf(fmaf(dvw, a[6], bb1.z), 0.f);
    o[7] = fmaxf(fmaf(dvw, a[7], bb1.w), 0.f);
    __half2 h0 = __floats2half2_rn(o[0], o[1]);
    __half2 h1 = __floats2half2_rn(o[2], o[3]);
    __half2 h2 = __floats2half2_rn(o[4], o[5]);
    __half2 h3 = __floats2half2_rn(o[6], o[7]);
    uint4 u = make_uint4(*(uint32_t*)&h0, *(uint32_t*)&h1, *(uint32_t*)&h2, *(uint32_t*)&h3);
    ((uint4*)(g_hh + (size_t)w * C1))[lane] = u;
}

// ---------------- fused gather2 + head (uniform loads, 8-deep MLP, PDL) ----------------
__global__ __launch_bounds__(1024) void gather2_head(
    const float* __restrict__ b_mu, const float* __restrict__ b_lv,
    const float* __restrict__ W_c, const float* __restrict__ b_c,
    const float* __restrict__ eps,
    float* __restrict__ out, int M)
{
    __shared__ float sWc[64 * 64];
    __shared__ float sz[32][64];
    int tid = threadIdx.x;
    // PDL prologue: stage Wc while gemm2 finishes
    for (int i = tid; i < 64 * 64; i += 1024) sWc[i] = W_c[i];
    cudaGridDependencySynchronize();
    __syncthreads();

    int w = (blockIdx.x * blockDim.x + tid) >> 5;
    if (w >= M) return;
    int lane = tid & 31;
    int wid = (tid >> 5);
    int base = g_rowptr[w];
    int deg = g_cnt[w];

    float a[4] = {0.f, 0.f, 0.f, 0.f};
    hacc4(a, ((const uint2*)(g_t2h + (size_t)w * C2))[lane]);

    const int* __restrict__ sl = g_srclist + base;
    int k = 0;
    for (; k + 8 <= deg; k += 8) {
        int s[8];
        uint2 u[8];
#pragma unroll
        for (int i = 0; i < 8; i++) s[i] = __ldg(sl + k + i);
#pragma unroll
        for (int i = 0; i < 8; i++) u[i] = ((const uint2*)(g_t2h + (size_t)s[i] * C2))[lane];
#pragma unroll
        for (int i = 0; i < 8; i++) hacc4(a, u[i]);
    }
    for (; k + 4 <= deg; k += 4) {
        int s0 = __ldg(sl + k);
        int s1 = __ldg(sl + k + 1);
        int s2 = __ldg(sl + k + 2);
        int s3 = __ldg(sl + k + 3);
        uint2 u0 = ((const uint2*)(g_t2h + (size_t)s0 * C2))[lane];
        uint2 u1 = ((const uint2*)(g_t2h + (size_t)s1 * C2))[lane];
        uint2 u2 = ((const uint2*)(g_t2h + (size_t)s2 * C2))[lane];
        uint2 u3 = ((const uint2*)(g_t2h + (size_t)s3 * C2))[lane];
        hacc4(a, u0); hacc4(a, u1); hacc4(a, u2); hacc4(a, u3);
    }
    for (; k < deg; k++) {
        int s0 = __ldg(sl + k);
        hacc4(a, ((const uint2*)(g_t2h + (size_t)s0 * C2))[lane]);
    }

    float dv = g_dinv[w];
    bool is_mu = lane < 16;
    int cm = is_mu ? lane * 4 : (lane - 16) * 4;
    float4 bb = is_mu ? ((const float4*)b_mu)[cm >> 2] : ((const float4*)b_lv)[cm >> 2];
    float v[4];
    v[0] = fmaf(dv, a[0], bb.x);
    v[1] = fmaf(dv, a[1], bb.y);
    v[2] = fmaf(dv, a[2], bb.z);
    v[3] = fmaf(dv, a[3], bb.w);

    size_t MO = (size_t)M * 64;
    float* dst = is_mu ? (out + MO + (size_t)w * 64 + cm)
                       : (out + 2 * MO + (size_t)w * 64 + cm);
    *(float4*)dst = make_float4(v[0], v[1], v[2], v[3]);

    float lv0 = __shfl_sync(0xffffffff, v[0], lane + 16);
    float lv1 = __shfl_sync(0xffffffff, v[1], lane + 16);
    float lv2 = __shfl_sync(0xffffffff, v[2], lane + 16);
    float lv3 = __shfl_sync(0xffffffff, v[3], lane + 16);
    if (is_mu) {
        float4 ep = *(const float4*)(eps + (size_t)w * 64 + cm);
        sz[wid][cm + 0] = fmaf(ep.x, __expf(0.5f * lv0), v[0]);
        sz[wid][cm + 1] = fmaf(ep.y, __expf(0.5f * lv1), v[1]);
        sz[wid][cm + 2] = fmaf(ep.z, __expf(0.5f * lv2), v[2]);
        sz[wid][cm + 3] = fmaf(ep.w, __expf(0.5f * lv3), v[3]);
    }
    __syncwarp();

    float s1 = b_c[lane];
    float s2 = b_c[lane + 32];
#pragma unroll 16
    for (int c = 0; c < 64; c++) {
        float zc = sz[wid][c];
        s1 = fmaf(zc, sWc[c * 64 + lane], s1);
        s2 = fmaf(zc, sWc[c * 64 + lane + 32], s2);
    }
    out[(size_t)w * 64 + lane] = s1;
    out[(size_t)w * 64 + lane + 32] = s2;
}

extern "C" void kernel_launch(void* const* d_in, const int* in_sizes, int n_in,
                              void* d_out, int out_size) {
    const float* x    = (const float*)d_in[0];
    const int*   ei   = (const int*)d_in[1];
    const float* W1   = (const float*)d_in[2];
    const float* b1   = (const float*)d_in[3];
    const float* W_mu = (const float*)d_in[4];
    const float* b_mu = (const float*)d_in[5];
    const float* W_lv = (const float*)d_in[6];
    const float* b_lv = (const float*)d_in[7];
    const float* W_c  = (const float*)d_in[8];
    const float* b_c  = (const float*)d_in[9];
    const float* eps  = (const float*)d_in[10];
    float* out = (float*)d_out;

    const int M = in_sizes[0] / 512;   // 100000
    const int E = in_sizes[1] / 2;     // 3200000

    float* dinv;
    __half *t1h, *hh, *t2h;
    cudaGetSymbolAddress((void**)&dinv, g_dinv);
    cudaGetSymbolAddress((void**)&t1h,  g_t1h);
    cudaGetSymbolAddress((void**)&hh,   g_hh);
    cudaGetSymbolAddress((void**)&t2h,  g_t2h);

    static cudaStream_t s2 = nullptr;
    static cudaEvent_t ev_fork = nullptr, ev_csr = nullptr;
    if (!s2) {
        cudaStreamCreateWithFlags(&s2, cudaStreamNonBlocking);
        cudaEventCreateWithFlags(&ev_fork, cudaEventDisableTiming);
        cudaEventCreateWithFlags(&ev_csr,  cudaEventDisableTiming);
    }

    // ---- fork: CSR build on s2, GEMM1 on main ----
    cudaEventRecord(ev_fork, 0);
    cudaStreamWaitEvent(s2, ev_fork, 0);

    zero_cnt  <<<(M + 255) / 256, 256, 0, s2>>>(M);
    count_deg <<<(E + 511) / 512, 512, 0, s2>>>(ei, E);
    scan_local<<<NBLK, SCAN_B, 0, s2>>>(M);
    scan_apply<<<(M + 255) / 256, 256, 0, s2>>>(M);
    fill_csr  <<<(E + 511) / 512, 512, 0, s2>>>(ei, E);
    cudaEventRecord(ev_csr, s2);

    // GEMM1: t1h = fp16(x @ W1), swizzled 1-D grid (4 col-tiles adjacent share A via L2)
    {
        int nbx = (M + TBM - 1) / TBM;
        int nby = C1 / TBN;   // 4
        gemm_h16<false><<<nbx * nby, 256>>>(x, 512, W1, W1, C1, nby, nby,
                                            t1h, C1, nullptr, M, 512);
    }

    cudaStreamWaitEvent(0, ev_csr, 0);
    gather1<<<(M * 32 + 255) / 256, 256>>>(b1, M);

    // GEMM2: t2h = dinv * (hh @ [W_mu | W_lv])
    {
        int nbx = (M + TBM - 1) / TBM;
        gemm_h16<true><<<nbx * 2, 256>>>(hh, C1, W_mu, W_lv, 64, 2, 1,
                                         t2h, C2, dinv, M, C1);
    }

    // gather2_head with PDL: prologue (Wc staging) overlaps gemm2 tail
    {
        cudaLaunchConfig_t cfg = {};
        cfg.gridDim = dim3((M * 32 + 1023) / 1024);
        cfg.blockDim = dim3(1024);
        cfg.dynamicSmemBytes = 0;
        cfg.stream = 0;
        cudaLaunchAttribute at[1];
        at[0].id = cudaLaunchAttributeProgrammaticStreamSerialization;
        at[0].val.programmaticStreamSerializationAllowed = 1;
        cfg.attrs = at;
        cfg.numAttrs = 1;
        cudaLaunchKernelEx(&cfg, gather2_head, b_mu, b_lv, W_c, b_c, eps, out, M);
    }
}

// round 15
// speedup vs baseline: 1.1052x; 1.0003x over previous
#include <cuda_runtime.h>
#include <cuda_fp16.h>
#include <cstddef>
#include <cstdint>

#define NNODES 100000
#define NEDGES 3200000
#define C1 256
#define C2 128
#define SCAN_B 1024
#define NBLK ((NNODES + SCAN_B - 1) / SCAN_B)   // 98

// ---- scratch (static device globals) ----
__device__ int g_cnt   [NNODES];
__device__ int g_rowptr[NNODES];
__device__ int g_cursor[NNODES];
__device__ int g_bsum  [NBLK];
__device__ int g_srclist[NEDGES];
__device__ __align__(16) float  g_dinv[NNODES];
__device__ __align__(16) __half g_t1h[(size_t)NNODES * C1];  // UNscaled fp16 x@W1
__device__ __align__(16) __half g_hh [(size_t)NNODES * C1];  // fp16 hidden
__device__ __align__(16) __half g_t2h[(size_t)NNODES * C2];  // dinv-scaled fp16 h@[Wmu|Wlv]

// ---------------- CSR build ----------------
__global__ void zero_cnt(int M) {
    int i = blockIdx.x * blockDim.x + threadIdx.x;
    if (i < M) g_cnt[i] = 0;
}
__global__ void count_deg(const int* __restrict__ ei, int E) {
    int e = blockIdx.x * blockDim.x + threadIdx.x;
    if (e < E) atomicAdd(&g_cnt[ei[(size_t)E + e]], 1);
}
__global__ __launch_bounds__(SCAN_B) void scan_local(int M) {
    __shared__ int sh[SCAN_B];
    int tid = threadIdx.x;
    int i = blockIdx.x * SCAN_B + tid;
    int v = (i < M) ? g_cnt[i] : 0;
    if (i < M) g_dinv[i] = rsqrtf((float)(v + 1));
    sh[tid] = v;
    __syncthreads();
#pragma unroll
    for (int off = 1; off < SCAN_B; off <<= 1) {
        int t = (tid >= off) ? sh[tid - off] : 0;
        __syncthreads();
        sh[tid] += t;
        __syncthreads();
    }
    if (i < M) g_rowptr[i] = sh[tid] - v;
    if (tid == SCAN_B - 1) g_bsum[blockIdx.x] = sh[tid];
}
__global__ void scan_apply(int M) {
    __shared__ int s_off;
    int seg = (blockIdx.x * 256) / SCAN_B;
    if (threadIdx.x < 32) {
        int acc = 0;
        for (int j = threadIdx.x; j < seg; j += 32) acc += g_bsum[j];
#pragma unroll
        for (int o = 16; o; o >>= 1) acc += __shfl_down_sync(0xffffffff, acc, o);
        if (threadIdx.x == 0) s_off = acc;
    }
    __syncthreads();
    int i = blockIdx.x * 256 + threadIdx.x;
    if (i < M) {
        int r = g_rowptr[i] + s_off;
        g_rowptr[i] = r;
        g_cursor[i] = r;
    }
}
__global__ void fill_csr(const int* __restrict__ ei, int E) {
    int e = blockIdx.x * blockDim.x + threadIdx.x;
    if (e < E) {
        int s = ei[e];
        int d = ei[(size_t)E + e];
        int pos = atomicAdd(&g_cursor[d], 1);
        g_srclist[pos] = s;
    }
}

// ---------------- fp16 MMA GEMM with ldmatrix (A fp32 or fp16) ----------------
#define TBM 128
#define TBN 64
#define TBK 32
#define AST 40
#define BST 72

__device__ __forceinline__ void ldsm_x4(uint32_t& r0, uint32_t& r1, uint32_t& r2, uint32_t& r3,
                                        const void* p) {
    uint32_t addr = (uint32_t)__cvta_generic_to_shared(p);
    asm volatile("ldmatrix.sync.aligned.m8n8.x4.shared.b16 {%0,%1,%2,%3}, [%4];"
                 : "=r"(r0), "=r"(r1), "=r"(r2), "=r"(r3) : "r"(addr));
}
__device__ __forceinline__ void ldsm_x2t(uint32_t& r0, uint32_t& r1, const void* p) {
    uint32_t addr = (uint32_t)__cvta_generic_to_shared(p);
    asm volatile("ldmatrix.sync.aligned.m8n8.x2.trans.shared.b16 {%0,%1}, [%2];"
                 : "=r"(r0), "=r"(r1) : "r"(addr));
}

template <bool AHALF>
__global__ __launch_bounds__(256) void gemm_h16(
    const void* __restrict__ Ap, int lda,
    const float* __restrict__ B1, const float* __restrict__ B2,
    int ldb, int nby, int nby1,
    __half* __restrict__ Ct, int ldc,
    const float* __restrict__ dinv, int M, int K)
{
    __shared__ __align__(16) __half As[2][TBM][AST];
    __shared__ __align__(16) __half Bs[2][TBK][BST];

    const int tid = threadIdx.x;
    const int lane = tid & 31;
    const int warp = tid >> 5;
    const int wm = warp & 3;
    const int wn = warp >> 2;
    const int gid = lane >> 2;
    const int q = lane & 3;

    const int by = blockIdx.x % nby;
    const int bx = blockIdx.x / nby;
    const int row0 = bx * TBM;

    const float* B = (by < nby1) ? B1 : B2;
    const int bcol0 = (by < nby1) ? by * TBN : (by - nby1) * TBN;
    const int ocol0 = by * TBN;

    float c[2][4][4];
#pragma unroll
    for (int mt = 0; mt < 2; mt++)
#pragma unroll
        for (int nt = 0; nt < 4; nt++)
#pragma unroll
            for (int r = 0; r < 4; r++) c[mt][nt][r] = 0.f;

    const int nk = K / TBK;
    float4 Av[4];
    uint4  Ah[2];
    float4 Bv[2];

    auto load_tile = [&](int t) {
        int k0 = t * TBK;
        if (AHALF) {
            const __half* A = (const __half*)Ap;
#pragma unroll
            for (int i = 0; i < 2; i++) {
                int idx = tid + i * 256;
                int r = idx >> 2;
                int c8 = (idx & 3) << 3;
                int gr = row0 + r;
                Ah[i] = (gr < M) ? *(const uint4*)(A + (size_t)gr * lda + k0 + c8)
                                 : make_uint4(0, 0, 0, 0);
            }
        } else {
            const float* A = (const float*)Ap;
#pragma unroll
            for (int i = 0; i < 4; i++) {
                int idx = tid + i * 256;
                int r = idx >> 3;
                int c4 = (idx & 7) << 2;
                int gr = row0 + r;
                Av[i] = (gr < M) ? *(const float4*)(A + (size_t)gr * lda + k0 + c4)
                                 : make_float4(0.f, 0.f, 0.f, 0.f);
            }
        }
#pragma unroll
        for (int i = 0; i < 2; i++) {
            int idx = tid + i * 256;
            int r = idx >> 4;
            int c4 = (idx & 15) << 2;
            Bv[i] = *(const float4*)(B + (size_t)(k0 + r) * ldb + bcol0 + c4);
        }
    };
    auto store_tile = [&](int buf) {
        if (AHALF) {
#pragma unroll
            for (int i = 0; i < 2; i++) {
                int idx = tid + i * 256;
                int r = idx >> 2;
                int c8 = (idx & 3) << 3;
                *(uint4*)&As[buf][r][c8] = Ah[i];
            }
        } else {
#pragma unroll
            for (int i = 0; i < 4; i++) {
                int idx = tid + i * 256;
                int r = idx >> 3;
                int c4 = (idx & 7) << 2;
                __half2 h01 = __floats2half2_rn(Av[i].x, Av[i].y);
                __half2 h23 = __floats2half2_rn(Av[i].z, Av[i].w);
                uint2 u = make_uint2(*(uint32_t*)&h01, *(uint32_t*)&h23);
                *(uint2*)&As[buf][r][c4] = u;
            }
        }
#pragma unroll
        for (int i = 0; i < 2; i++) {
            int idx = tid + i * 256;
            int r = idx >> 4;
            int c4 = (idx & 15) << 2;
            __half2 h01 = __floats2half2_rn(Bv[i].x, Bv[i].y);
            __half2 h23 = __floats2half2_rn(Bv[i].z, Bv[i].w);
            uint2 u = make_uint2(*(uint32_t*)&h01, *(uint32_t*)&h23);
            *(uint2*)&Bs[buf][r][c4] = u;
        }
    };

    load_tile(0);
    store_tile(0);
    __syncthreads();

    const int a_row = (lane & 15);
    const int a_koff = (lane >> 4) << 3;
    const int b_krow = (lane & 15);

    for (int t = 0; t < nk; t++) {
        int buf = t & 1;
        if (t + 1 < nk) load_tile(t + 1);

#pragma unroll
        for (int ks = 0; ks < TBK / 16; ks++) {
            int kb = ks * 16;
            uint32_t a[2][4], b[4][2];
#pragma unroll
            for (int mt = 0; mt < 2; mt++) {
                const __half* p = &As[buf][wm * 32 + mt * 16 + a_row][kb + a_koff];
                ldsm_x4(a[mt][0], a[mt][1], a[mt][2], a[mt][3], p);
            }
#pragma unroll
            for (int nt = 0; nt < 4; nt++) {
                const __half* p = &Bs[buf][kb + b_krow][wn * 32 + nt * 8];
                ldsm_x2t(b[nt][0], b[nt][1], p);
            }
#pragma unroll
            for (int mt = 0; mt < 2; mt++)
#pragma unroll
                for (int nt = 0; nt < 4; nt++)
                    asm volatile(
                        "mma.sync.aligned.m16n8k16.row.col.f32.f16.f16.f32 "
                        "{%0,%1,%2,%3}, {%4,%5,%6,%7}, {%8,%9}, {%0,%1,%2,%3};"
                        : "+f"(c[mt][nt][0]), "+f"(c[mt][nt][1]),
                          "+f"(c[mt][nt][2]), "+f"(c[mt][nt][3])
                        : "r"(a[mt][0]), "r"(a[mt][1]), "r"(a[mt][2]), "r"(a[mt][3]),
                          "r"(b[nt][0]), "r"(b[nt][1]));
        }

        if (t + 1 < nk) {
            store_tile(buf ^ 1);
            __syncthreads();
        }
    }

#pragma unroll
    for (int mt = 0; mt < 2; mt++) {
        int r0 = row0 + wm * 32 + mt * 16 + gid;
        int r1 = r0 + 8;
        float dv0 = 1.f, dv1 = 1.f;
        if (dinv) {
            dv0 = (r0 < M) ? dinv[r0] : 0.f;
            dv1 = (r1 < M) ? dinv[r1] : 0.f;
        }
#pragma unroll
        for (int nt = 0; nt < 4; nt++) {
            int cc = ocol0 + wn * 32 + nt * 8 + 2 * q;
            if (r0 < M)
                *(__half2*)(Ct + (size_t)r0 * ldc + cc) =
                    __floats2half2_rn(c[mt][nt][0] * dv0, c[mt][nt][1] * dv0);
            if (r1 < M)
                *(__half2*)(Ct + (size_t)r1 * ldc + cc) =
                    __floats2half2_rn(c[mt][nt][2] * dv1, c[mt][nt][3] * dv1);
        }
    }
}

// ---- fp16 accumulate helpers ----
__device__ __forceinline__ void hacc8s(float* a, uint4 u, float dv) {
    const __half2* hp = (const __half2*)&u;
#pragma unroll
    for (int i = 0; i < 4; i++) {
        float2 f = __half22float2(hp[i]);
        a[2 * i]     = fmaf(dv, f.x, a[2 * i]);
        a[2 * i + 1] = fmaf(dv, f.y, a[2 * i + 1]);
    }
}
__device__ __forceinline__ void hacc4(float* a, uint2 u) {
    const __half2* hp = (const __half2*)&u;
#pragma unroll
    for (int i = 0; i < 2; i++) {
        float2 f = __half22float2(hp[i]);
        a[2 * i] += f.x;
        a[2 * i + 1] += f.y;
    }
}

// ---------------- gather layer 1 (uniform loads, 8-deep MLP, PDL) ----------------
__global__ __launch_bounds__(256) void gather1(const float* __restrict__ b1, int M)
{
    // PDL prologue: CSR metadata only (ordered by the retained ev_csr event edge;
    // PDL relaxes only the same-stream gemm1 edge, whose output t1h is read after
    // cudaGridDependencySynchronize()).
    int w = (blockIdx.x * blockDim.x + threadIdx.x) >> 5;
    int lane = threadIdx.x & 31;
    int base = 0, deg = 0;
    float dvw = 0.f;
    if (w < M) {
        base = g_rowptr[w];
        deg = g_cnt[w];
        dvw = g_dinv[w];
    }
    cudaGridDependencySynchronize();
    if (w >= M) return;

    float a[8];
#pragma unroll
    for (int i = 0; i < 8; i++) a[i] = 0.f;
    hacc8s(a, ((const uint4*)(g_t1h + (size_t)w * C1))[lane], dvw);

    const int* __restrict__ sl = g_srclist + base;
    int k = 0;
    for (; k + 8 <= deg; k += 8) {
        int s[8];
        float d[8];
        uint4 u[8];
#pragma unroll
        for (int i = 0; i < 8; i++) s[i] = __ldg(sl + k + i);
#pragma unroll
        for (int i = 0; i < 8; i++) d[i] = __ldg(g_dinv + s[i]);
#pragma unroll
        for (int i = 0; i < 8; i++) u[i] = ((const uint4*)(g_t1h + (size_t)s[i] * C1))[lane];
#pragma unroll
        for (int i = 0; i < 8; i++) hacc8s(a, u[i], d[i]);
    }
    for (; k + 4 <= deg; k += 4) {
        int s0 = __ldg(sl + k);
        int s1 = __ldg(sl + k + 1);
        int s2 = __ldg(sl + k + 2);
        int s3 = __ldg(sl + k + 3);
        float d0 = __ldg(g_dinv + s0);
        float d1 = __ldg(g_dinv + s1);
        float d2 = __ldg(g_dinv + s2);
        float d3 = __ldg(g_dinv + s3);
        uint4 u0 = ((const uint4*)(g_t1h + (size_t)s0 * C1))[lane];
        uint4 u1 = ((const uint4*)(g_t1h + (size_t)s1 * C1))[lane];
        uint4 u2 = ((const uint4*)(g_t1h + (size_t)s2 * C1))[lane];
        uint4 u3 = ((const uint4*)(g_t1h + (size_t)s3 * C1))[lane];
        hacc8s(a, u0, d0); hacc8s(a, u1, d1); hacc8s(a, u2, d2); hacc8s(a, u3, d3);
    }
    for (; k < deg; k++) {
        int s0 = __ldg(sl + k);
        float d0 = __ldg(g_dinv + s0);
        hacc8s(a, ((const uint4*)(g_t1h + (size_t)s0 * C1))[lane], d0);
    }

    float4 bb0 = ((const float4*)b1)[lane * 2];
    float4 bb1 = ((const float4*)b1)[lane * 2 + 1];
    float o[8];
    o[0] = fmaxf(fmaf(dvw, a[0], bb0.x), 0.f);
    o[1] = fmaxf(fmaf(dvw, a[1], bb0.y), 0.f);
    o[2] = fmaxf(fmaf(dvw, a[2], bb0.z), 0.f);
    o[3] = fmaxf(fmaf(dvw, a[3], bb0.w), 0.f);
    o[4] = fmaxf(fmaf(dvw, a[4], bb1.x), 0.f);
    o[5] = fmaxf(fmaf(dvw, a[5], bb1.y), 0.f);
    o[6] = fmaxf(fmaf(dvw, a[6], bb1.z), 0.f);
    o[7] = fmaxf(fmaf(dvw, a[7], bb1.w), 0.f);
    __half2 h0 = __floats2half2_rn(o[0], o[1]);
    __half2 h1 = __floats2half2_rn(o[2], o[3]);
    __half2 h2 = __floats2half2_rn(o[4], o[5]);
    __half2 h3 = __floats2half2_rn(o[6], o[7]);
    uint4 u = make_uint4(*(uint32_t*)&h0, *(uint32_t*)&h1, *(uint32_t*)&h2, *(uint32_t*)&h3);
    ((uint4*)(g_hh + (size_t)w * C1))[lane] = u;
}

// ---------------- fused gather2 + head (uniform loads, 8-deep MLP, PDL) ----------------
__global__ __launch_bounds__(1024) void gather2_head(
    const float* __restrict__ b_mu, const float* __restrict__ b_lv,
    const float* __restrict__ W_c, const float* __restrict__ b_c,
    const float* __restrict__ eps,
    float* __restrict__ out, int M)
{
    __shared__ float sWc[64 * 64];
    __shared__ float sz[32][64];
    int tid = threadIdx.x;
    for (int i = tid; i < 64 * 64; i += 1024) sWc[i] = W_c[i];
    cudaGridDependencySynchronize();
    __syncthreads();

    int w = (blockIdx.x * blockDim.x + tid) >> 5;
    if (w >= M) return;
    int lane = tid & 31;
    int wid = (tid >> 5);
    int base = g_rowptr[w];
    int deg = g_cnt[w];

    float a[4] = {0.f, 0.f, 0.f, 0.f};
    hacc4(a, ((const uint2*)(g_t2h + (size_t)w * C2))[lane]);

    const int* __restrict__ sl = g_srclist + base;
    int k = 0;
    for (; k + 8 <= deg; k += 8) {
        int s[8];
        uint2 u[8];
#pragma unroll
        for (int i = 0; i < 8; i++) s[i] = __ldg(sl + k + i);
#pragma unroll
        for (int i = 0; i < 8; i++) u[i] = ((const uint2*)(g_t2h + (size_t)s[i] * C2))[lane];
#pragma unroll
        for (int i = 0; i < 8; i++) hacc4(a, u[i]);
    }
    for (; k + 4 <= deg; k += 4) {
        int s0 = __ldg(sl + k);
        int s1 = __ldg(sl + k + 1);
        int s2 = __ldg(sl + k + 2);
        int s3 = __ldg(sl + k + 3);
        uint2 u0 = ((const uint2*)(g_t2h + (size_t)s0 * C2))[lane];
        uint2 u1 = ((const uint2*)(g_t2h + (size_t)s1 * C2))[lane];
        uint2 u2 = ((const uint2*)(g_t2h + (size_t)s2 * C2))[lane];
        uint2 u3 = ((const uint2*)(g_t2h + (size_t)s3 * C2))[lane];
        hacc4(a, u0); hacc4(a, u1); hacc4(a, u2); hacc4(a, u3);
    }
    for (; k < deg; k++) {
        int s0 = __ldg(sl + k);
        hacc4(a, ((const uint2*)(g_t2h + (size_t)s0 * C2))[lane]);
    }

    float dv = g_dinv[w];
    bool is_mu = lane < 16;
    int cm = is_mu ? lane * 4 : (lane - 16) * 4;
    float4 bb = is_mu ? ((const float4*)b_mu)[cm >> 2] : ((const float4*)b_lv)[cm >> 2];
    float v[4];
    v[0] = fmaf(dv, a[0], bb.x);
    v[1] = fmaf(dv, a[1], bb.y);
    v[2] = fmaf(dv, a[2], bb.z);
    v[3] = fmaf(dv, a[3], bb.w);

    size_t MO = (size_t)M * 64;
    float* dst = is_mu ? (out + MO + (size_t)w * 64 + cm)
                       : (out + 2 * MO + (size_t)w * 64 + cm);
    *(float4*)dst = make_float4(v[0], v[1], v[2], v[3]);

    float lv0 = __shfl_sync(0xffffffff, v[0], lane + 16);
    float lv1 = __shfl_sync(0xffffffff, v[1], lane + 16);
    float lv2 = __shfl_sync(0xffffffff, v[2], lane + 16);
    float lv3 = __shfl_sync(0xffffffff, v[3], lane + 16);
    if (is_mu) {
        float4 ep = *(const float4*)(eps + (size_t)w * 64 + cm);
        sz[wid][cm + 0] = fmaf(ep.x, __expf(0.5f * lv0), v[0]);
        sz[wid][cm + 1] = fmaf(ep.y, __expf(0.5f * lv1), v[1]);
        sz[wid][cm + 2] = fmaf(ep.z, __expf(0.5f * lv2), v[2]);
        sz[wid][cm + 3] = fmaf(ep.w, __expf(0.5f * lv3), v[3]);
    }
    __syncwarp();

    float s1 = b_c[lane];
    float s2 = b_c[lane + 32];
#pragma unroll 16
    for (int c = 0; c < 64; c++) {
        float zc = sz[wid][c];
        s1 = fmaf(zc, sWc[c * 64 + lane], s1);
        s2 = fmaf(zc, sWc[c * 64 + lane + 32], s2);
    }
    out[(size_t)w * 64 + lane] = s1;
    out[(size_t)w * 64 + lane + 32] = s2;
}

extern "C" void kernel_launch(void* const* d_in, const int* in_sizes, int n_in,
                              void* d_out, int out_size) {
    const float* x    = (const float*)d_in[0];
    const int*   ei   = (const int*)d_in[1];
    const float* W1   = (const float*)d_in[2];
    const float* b1   = (const float*)d_in[3];
    const float* W_mu = (const float*)d_in[4];
    const float* b_mu = (const float*)d_in[5];
    const float* W_lv = (const float*)d_in[6];
    const float* b_lv = (const float*)d_in[7];
    const float* W_c  = (const float*)d_in[8];
    const float* b_c  = (const float*)d_in[9];
    const float* eps  = (const float*)d_in[10];
    float* out = (float*)d_out;

    const int M = in_sizes[0] / 512;   // 100000
    const int E = in_sizes[1] / 2;     // 3200000

    float* dinv;
    __half *t1h, *hh, *t2h;
    cudaGetSymbolAddress((void**)&dinv, g_dinv);
    cudaGetSymbolAddress((void**)&t1h,  g_t1h);
    cudaGetSymbolAddress((void**)&hh,   g_hh);
    cudaGetSymbolAddress((void**)&t2h,  g_t2h);

    static cudaStream_t s2 = nullptr;
    static cudaEvent_t ev_fork = nullptr, ev_csr = nullptr;
    if (!s2) {
        cudaStreamCreateWithFlags(&s2, cudaStreamNonBlocking);
        cudaEventCreateWithFlags(&ev_fork, cudaEventDisableTiming);
        cudaEventCreateWithFlags(&ev_csr,  cudaEventDisableTiming);
    }

    // ---- fork: CSR build on s2, GEMM1 on main ----
    cudaEventRecord(ev_fork, 0);
    cudaStreamWaitEvent(s2, ev_fork, 0);

    zero_cnt  <<<(M + 255) / 256, 256, 0, s2>>>(M);
    count_deg <<<(E + 511) / 512, 512, 0, s2>>>(ei, E);
    scan_local<<<NBLK, SCAN_B, 0, s2>>>(M);
    scan_apply<<<(M + 255) / 256, 256, 0, s2>>>(M);
    fill_csr  <<<(E + 511) / 512, 512, 0, s2>>>(ei, E);
    cudaEventRecord(ev_csr, s2);

    // GEMM1: t1h = fp16(x @ W1), swizzled 1-D grid (4 col-tiles adjacent share A via L2)
    {
        int nbx = (M + TBM - 1) / TBM;
        int nby = C1 / TBN;   // 4
        gemm_h16<false><<<nbx * nby, 256>>>(x, 512, W1, W1, C1, nby, nby,
                                            t1h, C1, nullptr, M, 512);
    }

    cudaStreamWaitEvent(0, ev_csr, 0);

    // gather1 with PDL: metadata prologue overlaps gemm1 tail (single change vs R14)
    {
        cudaLaunchConfig_t cfg = {};
        cfg.gridDim = dim3((M * 32 + 255) / 256);
        cfg.blockDim = dim3(256);
        cfg.dynamicSmemBytes = 0;
        cfg.stream = 0;
        cudaLaunchAttribute at[1];
        at[0].id = cudaLaunchAttributeProgrammaticStreamSerialization;
        at[0].val.programmaticStreamSerializationAllowed = 1;
        cfg.attrs = at;
        cfg.numAttrs = 1;
        cudaLaunchKernelEx(&cfg, gather1, b1, M);
    }

    // GEMM2: t2h = dinv * (hh @ [W_mu | W_lv])
    {
        int nbx = (M + TBM - 1) / TBM;
        gemm_h16<true><<<nbx * 2, 256>>>(hh, C1, W_mu, W_lv, 64, 2, 1,
                                         t2h, C2, dinv, M, C1);
    }

    // gather2_head with PDL: prologue (Wc staging) overlaps gemm2 tail
    {
        cudaLaunchConfig_t cfg = {};
        cfg.gridDim = dim3((M * 32 + 1023) / 1024);
        cfg.blockDim = dim3(1024);
        cfg.dynamicSmemBytes = 0;
        cfg.stream = 0;
        cudaLaunchAttribute at[1];
        at[0].id = cudaLaunchAttributeProgrammaticStreamSerialization;
        at[0].val.programmaticStreamSerializationAllowed = 1;
        cfg.attrs = at;
        cfg.numAttrs = 1;
        cudaLaunchKernelEx(&cfg, gather2_head, b_mu, b_lv, W_c, b_c, eps, out, M);
    }
}